// round 3
// baseline (speedup 1.0000x reference)
#include <cuda_runtime.h>
#include <cstdint>

// ---------------------------------------------------------------------------
// MultiHeadAttention, B=2 S=2048 D=1024 H=16 HD=64, fp32.
// Round 1: correct fp32 SIMT baseline.
//   k1: fused QKV projection GEMM (128x128x8 tile, 8x8/thread), writes
//       Q/K/V in [b,h,s,hd] layout.
//   k2: flash-attention, 1 thread per query row, online softmax, causal.
//   k3: output projection GEMM -> d_out.
// ---------------------------------------------------------------------------

constexpr int Bc  = 2;
constexpr int Sc  = 2048;
constexpr int Dc  = 1024;
constexpr int Hc  = 16;
constexpr int HDc = 64;
constexpr int Mc  = Bc * Sc;   // 4096 rows for the dense GEMMs

// Scratch (allocation-free rule: __device__ globals)
__device__ float g_Q[Bc * Hc * Sc * HDc];
__device__ float g_K[Bc * Hc * Sc * HDc];
__device__ float g_V[Bc * Hc * Sc * HDc];
__device__ float g_ctx[Mc * Dc];

// ---------------------------------------------------------------------------
// SGEMM body: C[M,N] = A[M,K] * W[K,N] + bias, M=4096, N=K=1024.
// BM=BN=128, BK=8, TM=TN=8, 256 threads. Register-prefetched global loads.
// SPLIT=true writes into [b,h,s,hd] layout (for Q/K/V).
// ---------------------------------------------------------------------------
template <bool SPLIT>
__device__ __forceinline__ void gemm_body(const float* __restrict__ A,
                                          const float* __restrict__ Bw,
                                          const float* __restrict__ bias,
                                          float* __restrict__ C) {
  constexpr int K = Dc;
  constexpr int N = Dc;
  __shared__ float As[8][128];
  __shared__ float Bs[8][128];

  const int tid  = threadIdx.x;
  const int tr   = tid >> 4;        // 0..15
  const int tc   = tid & 15;        // 0..15
  const int rowA = tid >> 1;        // 0..127
  const int colA = (tid & 1) << 2;  // 0 or 4
  const int rowB = tid >> 5;        // 0..7
  const int colB = (tid & 31) << 2; // 0..124

  const float* Ap = A + (size_t)(blockIdx.y * 128 + rowA) * K + colA;
  const float* Bp = Bw + (size_t)rowB * N + blockIdx.x * 128 + colB;

  float4 aReg = *(const float4*)Ap;
  float4 bReg = *(const float4*)Bp;

  float acc[8][8] = {};

  for (int k0 = 0; k0 < K; k0 += 8) {
    // fill smem from prefetch registers
    As[colA + 0][rowA] = aReg.x;
    As[colA + 1][rowA] = aReg.y;
    As[colA + 2][rowA] = aReg.z;
    As[colA + 3][rowA] = aReg.w;
    *(float4*)&Bs[rowB][colB] = bReg;
    __syncthreads();

    // prefetch next k-slab while computing this one
    if (k0 + 8 < K) {
      aReg = *(const float4*)(Ap + k0 + 8);
      bReg = *(const float4*)(Bp + (size_t)(k0 + 8) * N);
    }

#pragma unroll
    for (int k = 0; k < 8; ++k) {
      float4 m0 = *(const float4*)&As[k][tr * 8];
      float4 m1 = *(const float4*)&As[k][tr * 8 + 4];
      float4 n0 = *(const float4*)&Bs[k][tc * 8];
      float4 n1 = *(const float4*)&Bs[k][tc * 8 + 4];
      float rm[8] = {m0.x, m0.y, m0.z, m0.w, m1.x, m1.y, m1.z, m1.w};
      float rn[8] = {n0.x, n0.y, n0.z, n0.w, n1.x, n1.y, n1.z, n1.w};
#pragma unroll
      for (int i = 0; i < 8; ++i)
#pragma unroll
        for (int j = 0; j < 8; ++j)
          acc[i][j] = fmaf(rm[i], rn[j], acc[i][j]);
    }
    __syncthreads();
  }

  const int baseRow = blockIdx.y * 128 + tr * 8;
  const int baseCol = blockIdx.x * 128 + tc * 8;
#pragma unroll
  for (int i = 0; i < 8; ++i) {
    const int row = baseRow + i;
    if (SPLIT) {
      const int b    = row >> 11;     // / Sc
      const int sidx = row & 2047;    // % Sc
#pragma unroll
      for (int j = 0; j < 8; ++j) {
        const int col = baseCol + j;
        const int h   = col >> 6;     // / HDc
        const int hd  = col & 63;     // % HDc
        C[(((size_t)(b * Hc + h)) * Sc + sidx) * HDc + hd] =
            acc[i][j] + bias[col];
      }
    } else {
#pragma unroll
      for (int j = 0; j < 8; ++j) {
        const int col = baseCol + j;
        C[(size_t)row * N + col] = acc[i][j] + bias[col];
      }
    }
  }
}

// Fused QKV projection: gridDim.z in {0,1,2} selects (Wq,bq)->g_Q etc.
__global__ __launch_bounds__(256) void proj_kernel(
    const float* __restrict__ X,
    const float* __restrict__ Wq, const float* __restrict__ bq,
    const float* __restrict__ Wk, const float* __restrict__ bk,
    const float* __restrict__ Wv, const float* __restrict__ bv) {
  const float* W;
  const float* bias;
  float* out;
  if (blockIdx.z == 0)      { W = Wq; bias = bq; out = g_Q; }
  else if (blockIdx.z == 1) { W = Wk; bias = bk; out = g_K; }
  else                      { W = Wv; bias = bv; out = g_V; }
  gemm_body<true>(X, W, bias, out);
}

// Output projection: ctx @ Wo + bo -> d_out
__global__ __launch_bounds__(256) void out_kernel(
    const float* __restrict__ Wo, const float* __restrict__ bo,
    float* __restrict__ out) {
  gemm_body<false>(g_ctx, Wo, bo, out);
}

// ---------------------------------------------------------------------------
// Flash attention, causal. Block = 128 query rows (1 thread each),
// K/V tiles of 64 keys staged in smem (broadcast reads), online softmax
// over 32-key sub-tiles.
// grid: (S/128, B*H), block: 128 threads.
// ---------------------------------------------------------------------------
__global__ __launch_bounds__(128) void attn_kernel() {
  __shared__ float Ks[64][64];
  __shared__ float Vs[64][64];

  const int tid = threadIdx.x;
  const int bh  = blockIdx.y;           // b*H + h
  const int qb  = blockIdx.x;
  const int qi  = qb * 128 + tid;       // query row within this (b,h)

  // load my query row, pre-scaled by 1/sqrt(HD) = 0.125
  const float* Qp = g_Q + ((size_t)bh * Sc + qi) * HDc;
  float q[64];
#pragma unroll
  for (int d4 = 0; d4 < 16; ++d4) {
    float4 v = *(const float4*)(Qp + d4 * 4);
    q[d4 * 4 + 0] = v.x * 0.125f;
    q[d4 * 4 + 1] = v.y * 0.125f;
    q[d4 * 4 + 2] = v.z * 0.125f;
    q[d4 * 4 + 3] = v.w * 0.125f;
  }

  float o[64];
#pragma unroll
  for (int d = 0; d < 64; ++d) o[d] = 0.0f;
  float m = -1e30f;
  float l = 0.0f;

  const float* Kbase = g_K + (size_t)bh * Sc * HDc;
  const float* Vbase = g_V + (size_t)bh * Sc * HDc;

  const int ntiles = 2 * qb + 2;  // key tiles of 64 covering [0, qb*128+128)

  for (int t = 0; t < ntiles; ++t) {
    // cooperative coalesced load of K/V tiles
    for (int i = tid; i < 1024; i += 128) {
      const int r = i >> 4;
      const int c = (i & 15) << 2;
      *(float4*)&Ks[r][c] = *(const float4*)(Kbase + (size_t)(t * 64 + r) * 64 + c);
      *(float4*)&Vs[r][c] = *(const float4*)(Vbase + (size_t)(t * 64 + r) * 64 + c);
    }
    __syncthreads();

#pragma unroll
    for (int half = 0; half < 2; ++half) {
      const int kb = half * 32;
      float s[32];

      // scores: s[kk] = (q . K[kb+kk]) with causal mask
#pragma unroll
      for (int kk = 0; kk < 32; ++kk) {
        const float4* Kr = (const float4*)&Ks[kb + kk][0];
        float acc = 0.0f;
#pragma unroll
        for (int d4 = 0; d4 < 16; ++d4) {
          float4 kv = Kr[d4];
          acc = fmaf(q[4 * d4 + 0], kv.x, acc);
          acc = fmaf(q[4 * d4 + 1], kv.y, acc);
          acc = fmaf(q[4 * d4 + 2], kv.z, acc);
          acc = fmaf(q[4 * d4 + 3], kv.w, acc);
        }
        const int kglob = t * 64 + kb + kk;
        s[kk] = (kglob <= qi) ? acc : -1e30f;
      }

      // online softmax update
      float mnew = m;
#pragma unroll
      for (int kk = 0; kk < 32; ++kk) mnew = fmaxf(mnew, s[kk]);
      const float corr = __expf(m - mnew);
      m = mnew;
      l *= corr;
#pragma unroll
      for (int d = 0; d < 64; ++d) o[d] *= corr;

#pragma unroll
      for (int kk = 0; kk < 32; ++kk) {
        const float p = __expf(s[kk] - mnew);
        l += p;
        s[kk] = p;
      }

      // o += p . V
#pragma unroll
      for (int kk = 0; kk < 32; ++kk) {
        const float p = s[kk];
        const float4* Vr = (const float4*)&Vs[kb + kk][0];
#pragma unroll
        for (int d4 = 0; d4 < 16; ++d4) {
          float4 vv = Vr[d4];
          o[4 * d4 + 0] = fmaf(p, vv.x, o[4 * d4 + 0]);
          o[4 * d4 + 1] = fmaf(p, vv.y, o[4 * d4 + 1]);
          o[4 * d4 + 2] = fmaf(p, vv.z, o[4 * d4 + 2]);
          o[4 * d4 + 3] = fmaf(p, vv.w, o[4 * d4 + 3]);
        }
      }
    }
    __syncthreads();
  }

  // write ctx in [B,S,D] layout (D index = h*64 + d)
  const float inv = 1.0f / l;
  const int b = bh >> 4;
  const int h = bh & 15;
  float* op = g_ctx + ((size_t)(b * Sc + qi)) * Dc + h * HDc;
#pragma unroll
  for (int d4 = 0; d4 < 16; ++d4) {
    float4 v;
    v.x = o[4 * d4 + 0] * inv;
    v.y = o[4 * d4 + 1] * inv;
    v.z = o[4 * d4 + 2] * inv;
    v.w = o[4 * d4 + 3] * inv;
    *(float4*)(op + d4 * 4) = v;
  }
}

// ---------------------------------------------------------------------------
extern "C" void kernel_launch(void* const* d_in, const int* in_sizes, int n_in,
                              void* d_out, int out_size) {
  const float* x  = (const float*)d_in[0];
  const float* Wq = (const float*)d_in[1];
  const float* bq = (const float*)d_in[2];
  const float* Wk = (const float*)d_in[3];
  const float* bk = (const float*)d_in[4];
  const float* Wv = (const float*)d_in[5];
  const float* bv = (const float*)d_in[6];
  const float* Wo = (const float*)d_in[7];
  const float* bo = (const float*)d_in[8];
  float* out = (float*)d_out;

  // QKV projections: N/128 = 8, M/128 = 32, z = {Q,K,V}
  proj_kernel<<<dim3(8, 32, 3), 256>>>(x, Wq, bq, Wk, bk, Wv, bv);

  // attention: S/128 = 16 query blocks, B*H = 32 (b,h) pairs
  attn_kernel<<<dim3(16, 32), 128>>>();

  // output projection
  out_kernel<<<dim3(8, 32), 256>>>(Wo, bo, out);
}

// round 4
// speedup vs baseline: 1.7120x; 1.7120x over previous
#include <cuda_runtime.h>
#include <cstdint>

// ---------------------------------------------------------------------------
// MultiHeadAttention, B=2 S=2048 D=1024 H=16 HD=64, fp32.
// R3: register-tiled flash attention (64x64 tiles, 4x4 per thread).
//     GEMMs unchanged (measured at fp32 FFMA roofline already).
// ---------------------------------------------------------------------------

constexpr int Bc  = 2;
constexpr int Sc  = 2048;
constexpr int Dc  = 1024;
constexpr int Hc  = 16;
constexpr int HDc = 64;
constexpr int Mc  = Bc * Sc;

__device__ float g_Q[Bc * Hc * Sc * HDc];
__device__ float g_K[Bc * Hc * Sc * HDc];
__device__ float g_V[Bc * Hc * Sc * HDc];
__device__ float g_ctx[Mc * Dc];

// ---------------------------------------------------------------------------
// SGEMM body (unchanged from R2 — at fp32 roofline)
// ---------------------------------------------------------------------------
template <bool SPLIT>
__device__ __forceinline__ void gemm_body(const float* __restrict__ A,
                                          const float* __restrict__ Bw,
                                          const float* __restrict__ bias,
                                          float* __restrict__ C) {
  constexpr int K = Dc;
  constexpr int N = Dc;
  __shared__ float As[8][128];
  __shared__ float Bs[8][128];

  const int tid  = threadIdx.x;
  const int tr   = tid >> 4;
  const int tc   = tid & 15;
  const int rowA = tid >> 1;
  const int colA = (tid & 1) << 2;
  const int rowB = tid >> 5;
  const int colB = (tid & 31) << 2;

  const float* Ap = A + (size_t)(blockIdx.y * 128 + rowA) * K + colA;
  const float* Bp = Bw + (size_t)rowB * N + blockIdx.x * 128 + colB;

  float4 aReg = *(const float4*)Ap;
  float4 bReg = *(const float4*)Bp;

  float acc[8][8] = {};

  for (int k0 = 0; k0 < K; k0 += 8) {
    As[colA + 0][rowA] = aReg.x;
    As[colA + 1][rowA] = aReg.y;
    As[colA + 2][rowA] = aReg.z;
    As[colA + 3][rowA] = aReg.w;
    *(float4*)&Bs[rowB][colB] = bReg;
    __syncthreads();

    if (k0 + 8 < K) {
      aReg = *(const float4*)(Ap + k0 + 8);
      bReg = *(const float4*)(Bp + (size_t)(k0 + 8) * N);
    }

#pragma unroll
    for (int k = 0; k < 8; ++k) {
      float4 m0 = *(const float4*)&As[k][tr * 8];
      float4 m1 = *(const float4*)&As[k][tr * 8 + 4];
      float4 n0 = *(const float4*)&Bs[k][tc * 8];
      float4 n1 = *(const float4*)&Bs[k][tc * 8 + 4];
      float rm[8] = {m0.x, m0.y, m0.z, m0.w, m1.x, m1.y, m1.z, m1.w};
      float rn[8] = {n0.x, n0.y, n0.z, n0.w, n1.x, n1.y, n1.z, n1.w};
#pragma unroll
      for (int i = 0; i < 8; ++i)
#pragma unroll
        for (int j = 0; j < 8; ++j)
          acc[i][j] = fmaf(rm[i], rn[j], acc[i][j]);
    }
    __syncthreads();
  }

  const int baseRow = blockIdx.y * 128 + tr * 8;
  const int baseCol = blockIdx.x * 128 + tc * 8;
#pragma unroll
  for (int i = 0; i < 8; ++i) {
    const int row = baseRow + i;
    if (SPLIT) {
      const int b    = row >> 11;
      const int sidx = row & 2047;
#pragma unroll
      for (int j = 0; j < 8; ++j) {
        const int col = baseCol + j;
        const int h   = col >> 6;
        const int hd  = col & 63;
        C[(((size_t)(b * Hc + h)) * Sc + sidx) * HDc + hd] =
            acc[i][j] + bias[col];
      }
    } else {
#pragma unroll
      for (int j = 0; j < 8; ++j) {
        const int col = baseCol + j;
        C[(size_t)row * N + col] = acc[i][j] + bias[col];
      }
    }
  }
}

__global__ __launch_bounds__(256) void proj_kernel(
    const float* __restrict__ X,
    const float* __restrict__ Wq, const float* __restrict__ bq,
    const float* __restrict__ Wk, const float* __restrict__ bk,
    const float* __restrict__ Wv, const float* __restrict__ bv) {
  const float* W;
  const float* bias;
  float* out;
  if (blockIdx.z == 0)      { W = Wq; bias = bq; out = g_Q; }
  else if (blockIdx.z == 1) { W = Wk; bias = bk; out = g_K; }
  else                      { W = Wv; bias = bv; out = g_V; }
  gemm_body<true>(X, W, bias, out);
}

__global__ __launch_bounds__(256) void out_kernel(
    const float* __restrict__ Wo, const float* __restrict__ bo,
    float* __restrict__ out) {
  gemm_body<false>(g_ctx, Wo, bo, out);
}

// ---------------------------------------------------------------------------
// Flash attention, register-tiled.
// Block: 64 queries. 256 threads as 16(ty: query) x 16(tx: key/dim).
// Each thread: 4x4 score tile, 4x4 output tile.
// smem: Qs[64][64] natural, KPs[64][64] (K transposed, then aliased as P),
//       Vs[64][64] natural. Total = 48 KB exactly.
// grid: (32 qblocks reversed for load balance, B*H).
// ---------------------------------------------------------------------------
__global__ __launch_bounds__(256) void attn_kernel() {
  __shared__ float Qs[64][64];   // [q][d]
  __shared__ float KPs[64][64];  // phase 1: K^T [d][key]; phase 2: P [q][key]
  __shared__ float Vs[64][64];   // [key][d]

  const int tid = threadIdx.x;
  const int tx  = tid & 15;   // key / out-dim group
  const int ty  = tid >> 4;   // query group
  const int bh  = blockIdx.y;
  const int qb  = 31 - blockIdx.x;   // big blocks first
  const int q0  = qb * 64;

  const float* Qp    = g_Q + ((size_t)bh * Sc + q0) * HDc;
  const float* Kbase = g_K + (size_t)bh * Sc * HDc;
  const float* Vbase = g_V + (size_t)bh * Sc * HDc;

  // Load Q tile (pre-scaled by 1/sqrt(64))
  for (int i = tid; i < 1024; i += 256) {
    const int r  = i >> 4;
    const int c4 = (i & 15) << 2;
    float4 v = *(const float4*)(Qp + r * 64 + c4);
    v.x *= 0.125f; v.y *= 0.125f; v.z *= 0.125f; v.w *= 0.125f;
    *(float4*)&Qs[r][c4] = v;
  }

  float o[4][4] = {};
  float m[4], l[4];
#pragma unroll
  for (int i = 0; i < 4; ++i) { m[i] = -1e30f; l[i] = 0.0f; }

  for (int t = 0; t <= qb; ++t) {
    __syncthreads();  // previous tile's PV reads done (+ Qs visible on t=0)

    // Load K transposed: KPs[d][key]
    {
      const float* Kt = Kbase + (size_t)t * 64 * 64;
#pragma unroll
      for (int ii = 0; ii < 4; ++ii) {
        const int i  = tid + ii * 256;
        const int c4 = (((i >> 5) & 1) << 3) | (i & 7);   // 0..15
        const int r  = ((i >> 6) << 2) | ((i >> 3) & 3);  // 0..63
        float4 v = *(const float4*)(Kt + r * 64 + (c4 << 2));
        KPs[(c4 << 2) + 0][r] = v.x;
        KPs[(c4 << 2) + 1][r] = v.y;
        KPs[(c4 << 2) + 2][r] = v.z;
        KPs[(c4 << 2) + 3][r] = v.w;
      }
    }
    // Load V natural
    {
      const float* Vt = Vbase + (size_t)t * 64 * 64;
      for (int i = tid; i < 1024; i += 256) {
        const int r  = i >> 4;
        const int c4 = (i & 15) << 2;
        *(float4*)&Vs[r][c4] = *(const float4*)(Vt + r * 64 + c4);
      }
    }
    __syncthreads();

    // ---- QK^T: acc[i][j] = q(4ty+i) . k(4tx+j) ----
    float acc[4][4] = {};
#pragma unroll
    for (int k = 0; k < 64; k += 4) {
      float av[4][4], bv[4][4];
#pragma unroll
      for (int i = 0; i < 4; ++i) {
        float4 a = *(const float4*)&Qs[(ty << 2) + i][k];
        av[i][0] = a.x; av[i][1] = a.y; av[i][2] = a.z; av[i][3] = a.w;
      }
#pragma unroll
      for (int kk = 0; kk < 4; ++kk) {
        float4 b = *(const float4*)&KPs[k + kk][tx << 2];
        bv[kk][0] = b.x; bv[kk][1] = b.y; bv[kk][2] = b.z; bv[kk][3] = b.w;
      }
#pragma unroll
      for (int kk = 0; kk < 4; ++kk)
#pragma unroll
        for (int i = 0; i < 4; ++i)
#pragma unroll
          for (int j = 0; j < 4; ++j)
            acc[i][j] = fmaf(av[i][kk], bv[kk][j], acc[i][j]);
    }

    // causal mask (diagonal tile only)
    if (t == qb) {
#pragma unroll
      for (int i = 0; i < 4; ++i)
#pragma unroll
        for (int j = 0; j < 4; ++j)
          if ((tx << 2) + j > (ty << 2) + i) acc[i][j] = -1e30f;
    }

    // ---- online softmax ----
#pragma unroll
    for (int i = 0; i < 4; ++i) {
      float mi = fmaxf(fmaxf(acc[i][0], acc[i][1]),
                       fmaxf(acc[i][2], acc[i][3]));
#pragma unroll
      for (int off = 1; off < 16; off <<= 1)
        mi = fmaxf(mi, __shfl_xor_sync(0xffffffffu, mi, off));
      const float mnew = fmaxf(m[i], mi);
      const float corr = __expf(m[i] - mnew);
      m[i] = mnew;
#pragma unroll
      for (int j = 0; j < 4; ++j) acc[i][j] = __expf(acc[i][j] - mnew);
      float rs = acc[i][0] + acc[i][1] + acc[i][2] + acc[i][3];
#pragma unroll
      for (int off = 1; off < 16; off <<= 1)
        rs += __shfl_xor_sync(0xffffffffu, rs, off);
      l[i] = l[i] * corr + rs;
#pragma unroll
      for (int j = 0; j < 4; ++j) o[i][j] *= corr;
    }

    __syncthreads();  // all QK reads of KPs done

    // Write P tile into KPs (natural [q][key])
#pragma unroll
    for (int i = 0; i < 4; ++i) {
      float4 w;
      w.x = acc[i][0]; w.y = acc[i][1]; w.z = acc[i][2]; w.w = acc[i][3];
      *(float4*)&KPs[(ty << 2) + i][tx << 2] = w;
    }
    __syncthreads();  // P visible

    // ---- PV: o[i][j] += P(4ty+i, k) * V(k, 4tx+j) ----
#pragma unroll
    for (int k = 0; k < 64; k += 4) {
      float pv[4][4], vv[4][4];
#pragma unroll
      for (int i = 0; i < 4; ++i) {
        float4 p = *(const float4*)&KPs[(ty << 2) + i][k];
        pv[i][0] = p.x; pv[i][1] = p.y; pv[i][2] = p.z; pv[i][3] = p.w;
      }
#pragma unroll
      for (int kk = 0; kk < 4; ++kk) {
        float4 v = *(const float4*)&Vs[k + kk][tx << 2];
        vv[kk][0] = v.x; vv[kk][1] = v.y; vv[kk][2] = v.z; vv[kk][3] = v.w;
      }
#pragma unroll
      for (int kk = 0; kk < 4; ++kk)
#pragma unroll
        for (int i = 0; i < 4; ++i)
#pragma unroll
          for (int j = 0; j < 4; ++j)
            o[i][j] = fmaf(pv[i][kk], vv[kk][j], o[i][j]);
    }
  }

  // write ctx [B,S,D]; D col = h*64 + tx*4 + j
  const int b = bh >> 4;
  const int h = bh & 15;
#pragma unroll
  for (int i = 0; i < 4; ++i) {
    const float inv = 1.0f / l[i];
    const int q = q0 + (ty << 2) + i;
    float4 w;
    w.x = o[i][0] * inv; w.y = o[i][1] * inv;
    w.z = o[i][2] * inv; w.w = o[i][3] * inv;
    *(float4*)(g_ctx + ((size_t)(b * Sc + q)) * Dc + h * HDc + (tx << 2)) = w;
  }
}

// ---------------------------------------------------------------------------
extern "C" void kernel_launch(void* const* d_in, const int* in_sizes, int n_in,
                              void* d_out, int out_size) {
  const float* x  = (const float*)d_in[0];
  const float* Wq = (const float*)d_in[1];
  const float* bq = (const float*)d_in[2];
  const float* Wk = (const float*)d_in[3];
  const float* bk = (const float*)d_in[4];
  const float* Wv = (const float*)d_in[5];
  const float* bv = (const float*)d_in[6];
  const float* Wo = (const float*)d_in[7];
  const float* bo = (const float*)d_in[8];
  float* out = (float*)d_out;

  proj_kernel<<<dim3(8, 32, 3), 256>>>(x, Wq, bq, Wk, bk, Wv, bv);
  attn_kernel<<<dim3(32, 32), 256>>>();
  out_kernel<<<dim3(8, 32), 256>>>(Wo, bo, out);
}